// round 3
// baseline (speedup 1.0000x reference)
#include <cuda_runtime.h>
#include <math.h>

#define BB 2
#define EE 512
#define NN 4096
#define MM 4096

typedef unsigned long long u64;

// Scratch (static __device__ — allocation-free per harness rules)
__device__ float g_Q[BB * EE * NN];   // Qt: [b][f][n]  16 MB
__device__ float g_K[BB * EE * MM];   // Kt: [b][f][m]  16 MB
__device__ float g_kk[BB * MM];       // ||k||^2

// ---- packed f32x2 helpers (sm_100+ PTX) -----------------------------------
__device__ __forceinline__ u64 pack2(float x) {
    u64 r; asm("mov.b64 %0, {%1, %1};" : "=l"(r) : "f"(x)); return r;
}
__device__ __forceinline__ void fma2(u64& d, u64 a, u64 b) {
    asm("fma.rn.f32x2 %0, %1, %2, %3;" : "=l"(d) : "l"(a), "l"(b), "l"(d));
}
__device__ __forceinline__ float2 unpack2(u64 v) {
    float2 f; asm("mov.b64 {%0, %1}, %2;" : "=f"(f.x), "=f"(f.y) : "l"(v)); return f;
}

// ---------------------------------------------------------------------------
// Projection: Yt[b][f][n] = sum_e X[b][e][n] * W[f][e] + bias[f]   (transposed out)
// Block tile 64(n) x 128(f), 256 threads, per-thread 4x8 (f in fma2 pairs).
// ---------------------------------------------------------------------------
__global__ __launch_bounds__(256) void proj_kernel(
    const float* __restrict__ X, const float* __restrict__ W,
    const float* __restrict__ bias, int which)
{
    float* __restrict__ Y = which ? g_K : g_Q;
    __shared__ float Xs[32][64];    // [e][n]
    __shared__ float Ws[32][128];   // [e][f]

    const int tid = threadIdx.x;
    const int tx = tid & 15, ty = tid >> 4;
    const int n0 = blockIdx.x * 64;
    const int f0 = blockIdx.y * 128;
    const int b  = blockIdx.z;

    u64 acc[4][4];
#pragma unroll
    for (int i = 0; i < 4; ++i)
#pragma unroll
        for (int j = 0; j < 4; ++j) acc[i][j] = 0ull;

    const float* Xb = X + (size_t)b * EE * NN;

    for (int e0 = 0; e0 < EE; e0 += 32) {
        {   // Xs: 32 e-rows x 64 n-cols, direct copy
            const int r = tid >> 3;
            const int c = (tid & 7) * 8;
            const float4* s4 = (const float4*)(Xb + (size_t)(e0 + r) * NN + n0 + c);
            float4 v0 = s4[0], v1 = s4[1];
            *(float4*)&Xs[r][c]     = v0;
            *(float4*)&Xs[r][c + 4] = v1;
        }
        {   // Ws: transpose 128 f-rows x 32 e-cols -> [e][f]
            const int f  = tid >> 1;
            const int eo = (tid & 1) * 16;
            const float4* w4 = (const float4*)(W + (size_t)(f0 + f) * EE + e0 + eo);
#pragma unroll
            for (int k = 0; k < 4; ++k) {
                float4 v = w4[k];
                Ws[eo + 4 * k + 0][f] = v.x;
                Ws[eo + 4 * k + 1][f] = v.y;
                Ws[eo + 4 * k + 2][f] = v.z;
                Ws[eo + 4 * k + 3][f] = v.w;
            }
        }
        __syncthreads();
#pragma unroll 8
        for (int e = 0; e < 32; ++e) {
            float4 a = *(const float4*)&Xs[e][ty * 4];
            ulonglong2 b0 = *(const ulonglong2*)&Ws[e][tx * 4];
            ulonglong2 b1 = *(const ulonglong2*)&Ws[e][64 + tx * 4];
            u64 ap;
            ap = pack2(a.x);
            fma2(acc[0][0], ap, b0.x); fma2(acc[0][1], ap, b0.y);
            fma2(acc[0][2], ap, b1.x); fma2(acc[0][3], ap, b1.y);
            ap = pack2(a.y);
            fma2(acc[1][0], ap, b0.x); fma2(acc[1][1], ap, b0.y);
            fma2(acc[1][2], ap, b1.x); fma2(acc[1][3], ap, b1.y);
            ap = pack2(a.z);
            fma2(acc[2][0], ap, b0.x); fma2(acc[2][1], ap, b0.y);
            fma2(acc[2][2], ap, b1.x); fma2(acc[2][3], ap, b1.y);
            ap = pack2(a.w);
            fma2(acc[3][0], ap, b0.x); fma2(acc[3][1], ap, b0.y);
            fma2(acc[3][2], ap, b1.x); fma2(acc[3][3], ap, b1.y);
        }
        __syncthreads();
    }

    // epilogue: unpack, add bias, transposed store (f-major rows, n-contiguous)
    float v[4][8];
#pragma unroll
    for (int i = 0; i < 4; ++i) {
        float2 p;
        p = unpack2(acc[i][0]); v[i][0] = p.x; v[i][1] = p.y;
        p = unpack2(acc[i][1]); v[i][2] = p.x; v[i][3] = p.y;
        p = unpack2(acc[i][2]); v[i][4] = p.x; v[i][5] = p.y;
        p = unpack2(acc[i][3]); v[i][6] = p.x; v[i][7] = p.y;
    }
    float4 bs0 = *(const float4*)(bias + f0 + tx * 4);
    float4 bs1 = *(const float4*)(bias + f0 + 64 + tx * 4);
    float bv[8] = {bs0.x, bs0.y, bs0.z, bs0.w, bs1.x, bs1.y, bs1.z, bs1.w};
#pragma unroll
    for (int j = 0; j < 8; ++j) {
        const int f = (j < 4) ? (tx * 4 + j) : (64 + tx * 4 + (j - 4));
        float4 o = make_float4(v[0][j] + bv[j], v[1][j] + bv[j],
                               v[2][j] + bv[j], v[3][j] + bv[j]);
        *(float4*)(Y + ((size_t)b * EE + f0 + f) * NN + n0 + ty * 4) = o;
    }
}

// ---------------------------------------------------------------------------
// kk[b][m] = sum_f Kt[b][f][m]^2   (coalesced column sums over Kt)
// ---------------------------------------------------------------------------
__global__ __launch_bounds__(256) void kk_kernel()
{
    const int idx = blockIdx.x * 256 + threadIdx.x;   // over BB*MM
    const int b = idx >> 12;       // MM = 4096
    const int m = idx & (MM - 1);
    const float* p = g_K + (size_t)b * EE * MM + m;
    float s = 0.f;
#pragma unroll 8
    for (int f = 0; f < EE; ++f) {
        float v = p[(size_t)f * MM];
        s = fmaf(v, v, s);
    }
    g_kk[idx] = s;
}

// ---------------------------------------------------------------------------
// Flash attention: logits = 2 Q K^T - kk, online softmax, O = scores @ tgt^T
// CTA tile 64(n) x 256(m); 256 threads, per-thread 8x8 (m in fma2 pairs).
// Q tile (512x64) resident in SMEM; K streamed 32-e chunks, smem double-buffered.
// ---------------------------------------------------------------------------
__global__ __launch_bounds__(256, 1) void attn_kernel(
    const float* __restrict__ tgt, float* __restrict__ out_corr)
{
    extern __shared__ float sm[];
    float* Qs   = sm;                        // [512][64]
    float* Ks   = sm + EE * 64;              // [2][32][256]
    float* kks  = Ks + 2 * 32 * 256;         // [256]
    float* tgts = kks + 256;                 // [3][256]

    const int tid = threadIdx.x;
    const int tx = tid & 31, ty = tid >> 5;  // tx: m (8 cols), ty: n (8 rows)
    const int n0 = blockIdx.x * 64;
    const int b  = blockIdx.y;

    // Load Q tile (rows e, cols n) — straight copy from transposed Qt
    {
        const float* Qb = g_Q + (size_t)b * EE * NN + n0;
        const int r0 = tid >> 2;             // 0..63
        const int c4 = (tid & 3) * 4;        // float4 index
#pragma unroll
        for (int rr = 0; rr < EE; rr += 64) {
            const float4* s4 = (const float4*)(Qb + (size_t)(rr + r0) * NN) + c4;
            float4* d4 = (float4*)(Qs + (rr + r0) * 64) + c4;
            d4[0] = s4[0]; d4[1] = s4[1]; d4[2] = s4[2]; d4[3] = s4[3];
        }
    }

    float st_m[8], st_l[8], st_o[8][3];
#pragma unroll
    for (int i = 0; i < 8; ++i) {
        st_m[i] = -1e30f; st_l[i] = 0.f;
        st_o[i][0] = st_o[i][1] = st_o[i][2] = 0.f;
    }

    const float* Kb   = g_K + (size_t)b * EE * MM;
    const float* kkb  = g_kk + b * MM;
    const float* tgtb = tgt + (size_t)b * 3 * MM;

    // fill indexing: 8 threads per e-row, 8 float4 each
    const int fr = tid >> 3;                 // e-row 0..31
    const int fc = tid & 7;                  // float4 slot

    for (int m0 = 0; m0 < MM; m0 += 256) {
        __syncthreads();                     // prior tile's softmax done reading kks/tgts
        if (tid < 256) kks[tid] = kkb[m0 + tid];
        for (int t = tid; t < 768; t += 256)
            tgts[t] = tgtb[(t >> 8) * MM + m0 + (t & 255)];
        // fill chunk 0 -> buf 0
        {
            const float4* s4 = (const float4*)(Kb + (size_t)fr * MM + m0) + fc;
            float4* d4 = (float4*)(Ks + fr * 256) + fc;
            float4 tmp[8];
#pragma unroll
            for (int k = 0; k < 8; ++k) tmp[k] = s4[8 * k];
#pragma unroll
            for (int k = 0; k < 8; ++k) d4[8 * k] = tmp[k];
        }
        __syncthreads();

        u64 acc[8][4];
#pragma unroll
        for (int i = 0; i < 8; ++i)
#pragma unroll
            for (int j = 0; j < 4; ++j) acc[i][j] = 0ull;

        for (int c = 0; c < 16; ++c) {
            if (c < 15) {   // fill chunk c+1 into the other buffer
                const float* buf = Ks + ((c + 1) & 1) * (32 * 256);
                const float4* s4 = (const float4*)(Kb + (size_t)((c + 1) * 32 + fr) * MM + m0) + fc;
                float4* d4 = (float4*)(buf + fr * 256) + fc;
                float4 tmp[8];
#pragma unroll
                for (int k = 0; k < 8; ++k) tmp[k] = s4[8 * k];
#pragma unroll
                for (int k = 0; k < 8; ++k) d4[8 * k] = tmp[k];
            }
            const float* buf = Ks + (c & 1) * (32 * 256);
#pragma unroll 4
            for (int e = 0; e < 32; ++e) {
                const float* qrow = Qs + (c * 32 + e) * 64 + ty * 8;
                float4 a0 = *(const float4*)qrow;
                float4 a1 = *(const float4*)(qrow + 4);
                const float* krow = buf + e * 256;
                ulonglong2 kb0 = *(const ulonglong2*)(krow + tx * 4);
                ulonglong2 kb1 = *(const ulonglong2*)(krow + 128 + tx * 4);
                u64 ap;
                ap = pack2(a0.x);
                fma2(acc[0][0], ap, kb0.x); fma2(acc[0][1], ap, kb0.y);
                fma2(acc[0][2], ap, kb1.x); fma2(acc[0][3], ap, kb1.y);
                ap = pack2(a0.y);
                fma2(acc[1][0], ap, kb0.x); fma2(acc[1][1], ap, kb0.y);
                fma2(acc[1][2], ap, kb1.x); fma2(acc[1][3], ap, kb1.y);
                ap = pack2(a0.z);
                fma2(acc[2][0], ap, kb0.x); fma2(acc[2][1], ap, kb0.y);
                fma2(acc[2][2], ap, kb1.x); fma2(acc[2][3], ap, kb1.y);
                ap = pack2(a0.w);
                fma2(acc[3][0], ap, kb0.x); fma2(acc[3][1], ap, kb0.y);
                fma2(acc[3][2], ap, kb1.x); fma2(acc[3][3], ap, kb1.y);
                ap = pack2(a1.x);
                fma2(acc[4][0], ap, kb0.x); fma2(acc[4][1], ap, kb0.y);
                fma2(acc[4][2], ap, kb1.x); fma2(acc[4][3], ap, kb1.y);
                ap = pack2(a1.y);
                fma2(acc[5][0], ap, kb0.x); fma2(acc[5][1], ap, kb0.y);
                fma2(acc[5][2], ap, kb1.x); fma2(acc[5][3], ap, kb1.y);
                ap = pack2(a1.z);
                fma2(acc[6][0], ap, kb0.x); fma2(acc[6][1], ap, kb0.y);
                fma2(acc[6][2], ap, kb1.x); fma2(acc[6][3], ap, kb1.y);
                ap = pack2(a1.w);
                fma2(acc[7][0], ap, kb0.x); fma2(acc[7][1], ap, kb0.y);
                fma2(acc[7][2], ap, kb1.x); fma2(acc[7][3], ap, kb1.y);
            }
            __syncthreads();
        }

        // Online softmax update for this 256-m tile (8 m-cols per thread)
        float4 kk0 = *(const float4*)&kks[tx * 4];
        float4 kk1 = *(const float4*)&kks[128 + tx * 4];
        float4 t00 = *(const float4*)&tgts[tx * 4];
        float4 t01 = *(const float4*)&tgts[128 + tx * 4];
        float4 t10 = *(const float4*)&tgts[256 + tx * 4];
        float4 t11 = *(const float4*)&tgts[256 + 128 + tx * 4];
        float4 t20 = *(const float4*)&tgts[512 + tx * 4];
        float4 t21 = *(const float4*)&tgts[512 + 128 + tx * 4];
#pragma unroll
        for (int i = 0; i < 8; ++i) {
            float lg[8]; float2 p;
            p = unpack2(acc[i][0]); lg[0] = 2.f * p.x - kk0.x; lg[1] = 2.f * p.y - kk0.y;
            p = unpack2(acc[i][1]); lg[2] = 2.f * p.x - kk0.z; lg[3] = 2.f * p.y - kk0.w;
            p = unpack2(acc[i][2]); lg[4] = 2.f * p.x - kk1.x; lg[5] = 2.f * p.y - kk1.y;
            p = unpack2(acc[i][3]); lg[6] = 2.f * p.x - kk1.z; lg[7] = 2.f * p.y - kk1.w;
            float lmax = lg[0];
#pragma unroll
            for (int j = 1; j < 8; ++j) lmax = fmaxf(lmax, lg[j]);
            const float nm = fmaxf(st_m[i], lmax);
            const float sc = __expf(st_m[i] - nm);
            st_l[i] *= sc;
            st_o[i][0] *= sc; st_o[i][1] *= sc; st_o[i][2] *= sc;
            float pj[8];
#pragma unroll
            for (int j = 0; j < 8; ++j) pj[j] = __expf(lg[j] - nm);
#pragma unroll
            for (int j = 0; j < 8; ++j) st_l[i] += pj[j];
            st_o[i][0] += pj[0]*t00.x + pj[1]*t00.y + pj[2]*t00.z + pj[3]*t00.w
                        + pj[4]*t01.x + pj[5]*t01.y + pj[6]*t01.z + pj[7]*t01.w;
            st_o[i][1] += pj[0]*t10.x + pj[1]*t10.y + pj[2]*t10.z + pj[3]*t10.w
                        + pj[4]*t11.x + pj[5]*t11.y + pj[6]*t11.z + pj[7]*t11.w;
            st_o[i][2] += pj[0]*t20.x + pj[1]*t20.y + pj[2]*t20.z + pj[3]*t20.w
                        + pj[4]*t21.x + pj[5]*t21.y + pj[6]*t21.z + pj[7]*t21.w;
            st_m[i] = nm;
        }
    }

    // Merge the 32 per-row partial states across the warp (m dimension)
#pragma unroll
    for (int i = 0; i < 8; ++i) {
        float m = st_m[i], l = st_l[i];
        float o0 = st_o[i][0], o1 = st_o[i][1], o2 = st_o[i][2];
#pragma unroll
        for (int off = 16; off; off >>= 1) {
            float om = __shfl_xor_sync(0xffffffffu, m,  off);
            float ol = __shfl_xor_sync(0xffffffffu, l,  off);
            float p0 = __shfl_xor_sync(0xffffffffu, o0, off);
            float p1 = __shfl_xor_sync(0xffffffffu, o1, off);
            float p2 = __shfl_xor_sync(0xffffffffu, o2, off);
            const float nm = fmaxf(m, om);
            const float sa = __expf(m - nm);
            const float sb = __expf(om - nm);
            l  = l  * sa + ol * sb;
            o0 = o0 * sa + p0 * sb;
            o1 = o1 * sa + p1 * sb;
            o2 = o2 * sa + p2 * sb;
            m = nm;
        }
        if (tx == 0) {
            const int n = n0 + ty * 8 + i;
            const float inv = 1.f / l;
            out_corr[((size_t)b * 3 + 0) * NN + n] = o0 * inv;
            out_corr[((size_t)b * 3 + 1) * NN + n] = o1 * inv;
            out_corr[((size_t)b * 3 + 2) * NN + n] = o2 * inv;
        }
    }
}

// ---------------------------------------------------------------------------
__global__ void copy_src_kernel(const float* __restrict__ src, float* __restrict__ out)
{
    const int i = blockIdx.x * 256 + threadIdx.x;
    if (i < BB * 3 * NN) out[i] = src[i];
}

// ---------------------------------------------------------------------------
extern "C" void kernel_launch(void* const* d_in, const int* in_sizes, int n_in,
                              void* d_out, int out_size)
{
    const float* src_emb = (const float*)d_in[0];
    const float* tgt_emb = (const float*)d_in[1];
    const float* src     = (const float*)d_in[2];
    const float* tgt     = (const float*)d_in[3];
    const float* Wq      = (const float*)d_in[4];
    const float* bq      = (const float*)d_in[5];
    const float* Wk      = (const float*)d_in[6];
    const float* bk      = (const float*)d_in[7];
    float* out = (float*)d_out;

    const int corr_elems = BB * 3 * NN;
    const bool tuple_out = (out_size >= 2 * corr_elems);
    float* corr_out = tuple_out ? (out + corr_elems) : out;

    dim3 pg(NN / 64, EE / 128, BB);
    proj_kernel<<<pg, 256>>>(src_emb, Wq, bq, 0);
    proj_kernel<<<pg, 256>>>(tgt_emb, Wk, bk, 1);
    kk_kernel<<<BB * MM / 256, 256>>>();

    const int smem_bytes = (EE * 64 + 2 * 32 * 256 + 256 + 768) * sizeof(float);
    cudaFuncSetAttribute(attn_kernel, cudaFuncAttributeMaxDynamicSharedMemorySize,
                         smem_bytes);
    attn_kernel<<<dim3(NN / 64, BB), 256, smem_bytes>>>(tgt, corr_out);

    if (tuple_out)
        copy_src_kernel<<<(corr_elems + 255) / 256, 256>>>(src, out);
}

// round 5
// speedup vs baseline: 1.6329x; 1.6329x over previous
#include <cuda_runtime.h>
#include <cuda_bf16.h>
#include <stdint.h>

#define BB 2
#define EE 512
#define NN 4096
#define MM 4096

typedef unsigned long long u64;
typedef unsigned int u32;

// ---- scratch ---------------------------------------------------------------
__device__ __nv_bfloat16 g_Qhi[BB * NN * EE];
__device__ __nv_bfloat16 g_Qlo[BB * NN * EE];
__device__ __nv_bfloat16 g_Khi[BB * MM * EE];
__device__ __nv_bfloat16 g_Klo[BB * MM * EE];
__device__ float g_kk[BB * MM];
__device__ float g_pm[4 * BB * NN], g_pl[4 * BB * NN], g_po[4 * BB * NN * 3];

// ---- f32x2 helpers ---------------------------------------------------------
__device__ __forceinline__ u64 pack2(float x) {
    u64 r; asm("mov.b64 %0, {%1, %1};" : "=l"(r) : "f"(x)); return r;
}
__device__ __forceinline__ void fma2(u64& d, u64 a, u64 b) {
    asm("fma.rn.f32x2 %0, %1, %2, %3;" : "=l"(d) : "l"(a), "l"(b), "l"(d));
}
__device__ __forceinline__ float2 unpack2(u64 v) {
    float2 f; asm("mov.b64 {%0, %1}, %2;" : "=f"(f.x), "=f"(f.y) : "l"(v)); return f;
}

// ---- PTX helpers (all portable, no 'a'-features) ---------------------------
__device__ __forceinline__ u32 smem_u32(const void* p) {
    u32 a;
    asm("{ .reg .u64 t; cvta.to.shared.u64 t, %1; cvt.u32.u64 %0, t; }" : "=r"(a) : "l"(p));
    return a;
}
__device__ __forceinline__ void cp16(u32 dst, const void* src) {
    asm volatile("cp.async.cg.shared.global [%0], [%1], 16;" :: "r"(dst), "l"(src) : "memory");
}
#define CP_COMMIT() asm volatile("cp.async.commit_group;" ::: "memory")
#define CP_WAIT(n)  asm volatile("cp.async.wait_group %0;" :: "n"(n) : "memory")

__device__ __forceinline__ void ldsm4(u32* r, u32 a) {
    asm volatile("ldmatrix.sync.aligned.m8n8.x4.shared.b16 {%0,%1,%2,%3}, [%4];"
                 : "=r"(r[0]), "=r"(r[1]), "=r"(r[2]), "=r"(r[3]) : "r"(a));
}
__device__ __forceinline__ void mma16816(float* c, const u32* a, const u32* b) {
    asm volatile(
        "mma.sync.aligned.m16n8k16.row.col.f32.bf16.bf16.f32 "
        "{%0,%1,%2,%3}, {%4,%5,%6,%7}, {%8,%9}, {%0,%1,%2,%3};"
        : "+f"(c[0]), "+f"(c[1]), "+f"(c[2]), "+f"(c[3])
        : "r"(a[0]), "r"(a[1]), "r"(a[2]), "r"(a[3]), "r"(b[0]), "r"(b[1]));
}
__device__ __forceinline__ u32 bf2_u32(float a, float b) {
    __nv_bfloat162 t = __floats2bfloat162_rn(a, b);
    return *reinterpret_cast<u32*>(&t);
}

// ---------------------------------------------------------------------------
// Projection -> bf16 hi/lo [b][n][e]
// ---------------------------------------------------------------------------
__global__ __launch_bounds__(256) void proj_kernel(
    const float* __restrict__ X, const float* __restrict__ W,
    const float* __restrict__ bias, int which)
{
    __nv_bfloat16* __restrict__ Yh = which ? g_Khi : g_Qhi;
    __nv_bfloat16* __restrict__ Yl = which ? g_Klo : g_Qlo;
    __shared__ float Xs[32][64];
    __shared__ float Ws[32][128];

    const int tid = threadIdx.x;
    const int tx = tid & 15, ty = tid >> 4;
    const int n0 = blockIdx.x * 64, f0 = blockIdx.y * 128, b = blockIdx.z;

    u64 acc[4][4];
#pragma unroll
    for (int i = 0; i < 4; ++i)
#pragma unroll
        for (int j = 0; j < 4; ++j) acc[i][j] = 0ull;

    const float* Xb = X + (size_t)b * EE * NN;
    for (int e0 = 0; e0 < EE; e0 += 32) {
        {
            const int r = tid >> 3, c = (tid & 7) * 8;
            const float4* s4 = (const float4*)(Xb + (size_t)(e0 + r) * NN + n0 + c);
            float4 v0 = s4[0], v1 = s4[1];
            *(float4*)&Xs[r][c] = v0; *(float4*)&Xs[r][c + 4] = v1;
        }
        {
            const int f = tid >> 1, eo = (tid & 1) * 16;
            const float4* w4 = (const float4*)(W + (size_t)(f0 + f) * EE + e0 + eo);
#pragma unroll
            for (int k = 0; k < 4; ++k) {
                float4 v = w4[k];
                Ws[eo + 4*k + 0][f] = v.x; Ws[eo + 4*k + 1][f] = v.y;
                Ws[eo + 4*k + 2][f] = v.z; Ws[eo + 4*k + 3][f] = v.w;
            }
        }
        __syncthreads();
#pragma unroll 8
        for (int e = 0; e < 32; ++e) {
            float4 a = *(const float4*)&Xs[e][ty * 4];
            ulonglong2 b0 = *(const ulonglong2*)&Ws[e][tx * 4];
            ulonglong2 b1 = *(const ulonglong2*)&Ws[e][64 + tx * 4];
            u64 ap;
            ap = pack2(a.x);
            fma2(acc[0][0], ap, b0.x); fma2(acc[0][1], ap, b0.y);
            fma2(acc[0][2], ap, b1.x); fma2(acc[0][3], ap, b1.y);
            ap = pack2(a.y);
            fma2(acc[1][0], ap, b0.x); fma2(acc[1][1], ap, b0.y);
            fma2(acc[1][2], ap, b1.x); fma2(acc[1][3], ap, b1.y);
            ap = pack2(a.z);
            fma2(acc[2][0], ap, b0.x); fma2(acc[2][1], ap, b0.y);
            fma2(acc[2][2], ap, b1.x); fma2(acc[2][3], ap, b1.y);
            ap = pack2(a.w);
            fma2(acc[3][0], ap, b0.x); fma2(acc[3][1], ap, b0.y);
            fma2(acc[3][2], ap, b1.x); fma2(acc[3][3], ap, b1.y);
        }
        __syncthreads();
    }

    float4 bs0 = *(const float4*)(bias + f0 + tx * 4);
    float4 bs1 = *(const float4*)(bias + f0 + 64 + tx * 4);
    float bv[8] = {bs0.x, bs0.y, bs0.z, bs0.w, bs1.x, bs1.y, bs1.z, bs1.w};
#pragma unroll
    for (int i = 0; i < 4; ++i) {
        float y[8]; float2 p;
        p = unpack2(acc[i][0]); y[0] = p.x + bv[0]; y[1] = p.y + bv[1];
        p = unpack2(acc[i][1]); y[2] = p.x + bv[2]; y[3] = p.y + bv[3];
        p = unpack2(acc[i][2]); y[4] = p.x + bv[4]; y[5] = p.y + bv[5];
        p = unpack2(acc[i][3]); y[6] = p.x + bv[6]; y[7] = p.y + bv[7];
        float hf[8], lf[8];
#pragma unroll
        for (int j = 0; j < 8; ++j) {
            __nv_bfloat16 h = __float2bfloat16_rn(y[j]);
            hf[j] = __bfloat162float(h);
            lf[j] = y[j] - hf[j];
        }
        const size_t rowo = ((size_t)b * NN + n0 + ty * 4 + i) * EE;
#pragma unroll
        for (int g = 0; g < 2; ++g) {
            uint2 ph, pl;
            ph.x = bf2_u32(hf[g*4+0], hf[g*4+1]); ph.y = bf2_u32(hf[g*4+2], hf[g*4+3]);
            pl.x = bf2_u32(lf[g*4+0], lf[g*4+1]); pl.y = bf2_u32(lf[g*4+2], lf[g*4+3]);
            const size_t off = rowo + f0 + g * 64 + tx * 4;
            *(uint2*)(Yh + off) = ph;
            *(uint2*)(Yl + off) = pl;
        }
    }
}

// ---------------------------------------------------------------------------
__global__ __launch_bounds__(256) void kk_kernel()
{
    const int row = blockIdx.x * 8 + (threadIdx.x >> 5);
    const int lane = threadIdx.x & 31;
    const uint4* h4 = (const uint4*)(g_Khi + (size_t)row * EE);
    const uint4* l4 = (const uint4*)(g_Klo + (size_t)row * EE);
    float s = 0.f;
#pragma unroll
    for (int it = 0; it < 2; ++it) {
        uint4 h = h4[lane + it * 32], l = l4[lane + it * 32];
        const __nv_bfloat162* hp = (const __nv_bfloat162*)&h;
        const __nv_bfloat162* lp = (const __nv_bfloat162*)&l;
#pragma unroll
        for (int k = 0; k < 4; ++k) {
            float2 fh = __bfloat1622float2(hp[k]);
            float2 fl = __bfloat1622float2(lp[k]);
            float x = fh.x + fl.x, y = fh.y + fl.y;
            s = fmaf(x, x, fmaf(y, y, s));
        }
    }
#pragma unroll
    for (int off = 16; off; off >>= 1) s += __shfl_xor_sync(0xffffffffu, s, off);
    if (lane == 0) g_kk[row] = s;
}

// ---------------------------------------------------------------------------
// mma.sync attention. grid 128: b = bx>>6, q-tile = bx&63 (64 rows).
// CTA 64q x 256k tiles; 8 warps = 2(q) x 4(k); warp 32x64; 3-term bf16 split.
// ---------------------------------------------------------------------------
#define QPITCH 1040
#define KPITCH 80
#define SM_QH 0
#define SM_QL 66560
#define SM_K  133120          /* [2 buf][hi/lo][256][KPITCH] */
#define KBUF  40960
#define KLO_OFF 20480
#define SM_KKS 215040
#define SM_TGS 216064
#define SMEM_TOTAL 219136

__global__ __launch_bounds__(256, 1) void attn_kernel(const float* __restrict__ tgt)
{
    extern __shared__ char smraw[];
    const u32 S = smem_u32(smraw);
    const int tid = threadIdx.x, wid = tid >> 5, lane = tid & 31;
    const int qg = wid >> 2, kg = wid & 3;
    const int b = blockIdx.x >> 6, n0 = (blockIdx.x & 63) * 64;

    // ---- Q tile fill (once): 64 rows x 512 e, hi+lo, pitch 1040 ----
    {
        const char* qh = (const char*)(g_Qhi + (size_t)(b * NN + n0) * EE);
        const char* ql = (const char*)(g_Qlo + (size_t)(b * NN + n0) * EE);
        for (int i = tid; i < 4096; i += 256) {
            const int row = i >> 6, g = (i & 63) * 16;
            cp16(S + SM_QH + row * QPITCH + g, qh + row * 1024 + g);
            cp16(S + SM_QL + row * QPITCH + g, ql + row * 1024 + g);
        }
        CP_COMMIT(); CP_WAIT(0);
        __syncthreads();
    }

    // lane-constant ldmatrix offsets
    const int laneQrow = (lane & 7) + ((lane >> 3) & 1) * 8;
    const int laneQcolB = (lane >> 4) * 16;
    const int laneKn = (lane & 7) + ((lane >> 4) & 1) * 8;
    const int laneKeB = ((lane >> 3) & 1) * 16;
    u32 qoff[2], koff[4];
#pragma unroll
    for (int mt = 0; mt < 2; ++mt)
        qoff[mt] = (u32)((qg * 32 + mt * 16 + laneQrow) * QPITCH + laneQcolB);
#pragma unroll
    for (int np = 0; np < 4; ++np)
        koff[np] = (u32)((kg * 64 + np * 16 + laneKn) * KPITCH + laneKeB);

    float* kks = (float*)(smraw + SM_KKS);
    float* tgs = (float*)(smraw + SM_TGS);
    const float* kkb = g_kk + b * MM;
    const float* tgtb = tgt + (size_t)b * 3 * MM;

    float stm[4], stl[4], so[4][3];
#pragma unroll
    for (int r = 0; r < 4; ++r) {
        stm[r] = -1e30f; stl[r] = 0.f;
        so[r][0] = so[r][1] = so[r][2] = 0.f;
    }

    for (int t = 0; t < 16; ++t) {
        const int m0 = t * 256;
        const char* khg = (const char*)(g_Khi + (size_t)(b * MM + m0) * EE);
        const char* klg = (const char*)(g_Klo + (size_t)(b * MM + m0) * EE);
        __syncthreads();                       // prior epilogue done with kks/tgs
        kks[tid] = kkb[m0 + tid];
        for (int i = tid; i < 768; i += 256)
            tgs[i] = tgtb[(i >> 8) * MM + m0 + (i & 255)];

        float acc[2][8][4];
#pragma unroll
        for (int mt = 0; mt < 2; ++mt)
#pragma unroll
            for (int nt = 0; nt < 8; ++nt)
#pragma unroll
                for (int j = 0; j < 4; ++j) acc[mt][nt][j] = 0.f;

        // fill chunk 0 -> buf 0
        for (int i = tid; i < 1024; i += 256) {
            const int key = i >> 2, g = (i & 3) * 16;
            cp16(S + SM_K + key * KPITCH + g, khg + key * 1024 + g);
            cp16(S + SM_K + KLO_OFF + key * KPITCH + g, klg + key * 1024 + g);
        }
        CP_COMMIT();

        for (int c = 0; c < 16; ++c) {
            if (c < 15) {
                const u32 dst = S + SM_K + ((c + 1) & 1) * KBUF;
                const int go = (c + 1) * 64;
                for (int i = tid; i < 1024; i += 256) {
                    const int key = i >> 2, g = (i & 3) * 16;
                    cp16(dst + key * KPITCH + g, khg + key * 1024 + go + g);
                    cp16(dst + KLO_OFF + key * KPITCH + g, klg + key * 1024 + go + g);
                }
                CP_COMMIT(); CP_WAIT(1);
            } else {
                CP_WAIT(0);
            }
            __syncthreads();
            const u32 KB = S + SM_K + (c & 1) * KBUF;
#pragma unroll
            for (int s = 0; s < 2; ++s) {
                const u32 qeB = (u32)(c * 64 + s * 32);
                const u32 keB = (u32)(s * 32);
                u32 ah[2][4], al[2][4], bh[4][4], bl[4][4];
#pragma unroll
                for (int mt = 0; mt < 2; ++mt) {
                    ldsm4(ah[mt], S + SM_QH + qoff[mt] + qeB);
                    ldsm4(al[mt], S + SM_QL + qoff[mt] + qeB);
                }
#pragma unroll
                for (int np = 0; np < 4; ++np) {
                    ldsm4(bh[np], KB + koff[np] + keB);
                    ldsm4(bl[np], KB + KLO_OFF + koff[np] + keB);
                }
#pragma unroll
                for (int mt = 0; mt < 2; ++mt)
#pragma unroll
                    for (int np = 0; np < 4; ++np) {
                        mma16816(acc[mt][np*2+0], ah[mt], &bh[np][0]);
                        mma16816(acc[mt][np*2+0], ah[mt], &bl[np][0]);
                        mma16816(acc[mt][np*2+0], al[mt], &bh[np][0]);
                        mma16816(acc[mt][np*2+1], ah[mt], &bh[np][2]);
                        mma16816(acc[mt][np*2+1], ah[mt], &bl[np][2]);
                        mma16816(acc[mt][np*2+1], al[mt], &bh[np][2]);
                    }
            }
            __syncthreads();
        }

        // ---- epilogue: online softmax, per-thread (4 rows x 16 cols) ----
#pragma unroll
        for (int mt = 0; mt < 2; ++mt)
#pragma unroll
            for (int h = 0; h < 2; ++h) {
                const int r = mt * 2 + h;
                float lg[16], vmax = -1e30f;
#pragma unroll
                for (int nt = 0; nt < 8; ++nt) {
                    const int cb = kg * 64 + nt * 8 + (lane & 3) * 2;
                    lg[2*nt]   = fmaf(2.f, acc[mt][nt][h*2+0], -kks[cb]);
                    lg[2*nt+1] = fmaf(2.f, acc[mt][nt][h*2+1], -kks[cb+1]);
                    vmax = fmaxf(vmax, fmaxf(lg[2*nt], lg[2*nt+1]));
                }
                if (vmax >= stm[r] - 30.f) {       // skip: adds < 3e-9 rel error
                    const float nm = fmaxf(stm[r], vmax);
                    const float sc = __expf(stm[r] - nm);
                    stl[r] *= sc; so[r][0] *= sc; so[r][1] *= sc; so[r][2] *= sc;
#pragma unroll
                    for (int j = 0; j < 16; ++j) {
                        const int cb = kg * 64 + (j >> 1) * 8 + (lane & 3) * 2 + (j & 1);
                        const float p = __expf(lg[j] - nm);
                        stl[r] += p;
                        so[r][0] = fmaf(p, tgs[cb], so[r][0]);
                        so[r][1] = fmaf(p, tgs[256 + cb], so[r][1]);
                        so[r][2] = fmaf(p, tgs[512 + cb], so[r][2]);
                    }
                    stm[r] = nm;
                }
            }
    }

    // ---- merge across the 4 lanes sharing each row, write partials ----
#pragma unroll
    for (int mt = 0; mt < 2; ++mt)
#pragma unroll
        for (int h = 0; h < 2; ++h) {
            const int r = mt * 2 + h;
            float m = stm[r], l = stl[r];
            float o0 = so[r][0], o1 = so[r][1], o2 = so[r][2];
#pragma unroll
            for (int off = 1; off < 4; off <<= 1) {
                float om = __shfl_xor_sync(0xffffffffu, m,  off, 4);
                float ol = __shfl_xor_sync(0xffffffffu, l,  off, 4);
                float p0 = __shfl_xor_sync(0xffffffffu, o0, off, 4);
                float p1 = __shfl_xor_sync(0xffffffffu, o1, off, 4);
                float p2 = __shfl_xor_sync(0xffffffffu, o2, off, 4);
                const float nm = fmaxf(m, om);
                const float sa = __expf(m - nm), sb = __expf(om - nm);
                l = l * sa + ol * sb;
                o0 = o0 * sa + p0 * sb; o1 = o1 * sa + p1 * sb; o2 = o2 * sa + p2 * sb;
                m = nm;
            }
            if ((lane & 3) == 0) {
                const int n = n0 + qg * 32 + mt * 16 + h * 8 + (lane >> 2);
                const size_t pidx = (size_t)kg * (BB * NN) + (size_t)b * NN + n;
                g_pm[pidx] = m; g_pl[pidx] = l;
                g_po[3 * pidx + 0] = o0; g_po[3 * pidx + 1] = o1; g_po[3 * pidx + 2] = o2;
            }
        }
}

// ---------------------------------------------------------------------------
__global__ void merge_kernel(float* __restrict__ out_corr)
{
    const int idx = blockIdx.x * 256 + threadIdx.x;
    if (idx >= BB * NN) return;
    const int b = idx >> 12, n = idx & (NN - 1);
    float m = -1e30f;
#pragma unroll
    for (int s = 0; s < 4; ++s) m = fmaxf(m, g_pm[s * BB * NN + idx]);
    float l = 0.f, o0 = 0.f, o1 = 0.f, o2 = 0.f;
#pragma unroll
    for (int s = 0; s < 4; ++s) {
        const size_t p = (size_t)s * BB * NN + idx;
        const float w = __expf(g_pm[p] - m);
        l += g_pl[p] * w;
        o0 += g_po[3 * p + 0] * w; o1 += g_po[3 * p + 1] * w; o2 += g_po[3 * p + 2] * w;
    }
    const float inv = 1.f / l;
    out_corr[((size_t)b * 3 + 0) * NN + n] = o0 * inv;
    out_corr[((size_t)b * 3 + 1) * NN + n] = o1 * inv;
    out_corr[((size_t)b * 3 + 2) * NN + n] = o2 * inv;
}

__global__ void copy_src_kernel(const float* __restrict__ src, float* __restrict__ out)
{
    const int i = blockIdx.x * 256 + threadIdx.x;
    if (i < BB * 3 * NN) out[i] = src[i];
}

// ---------------------------------------------------------------------------
extern "C" void kernel_launch(void* const* d_in, const int* in_sizes, int n_in,
                              void* d_out, int out_size)
{
    const float* src_emb = (const float*)d_in[0];
    const float* tgt_emb = (const float*)d_in[1];
    const float* src     = (const float*)d_in[2];
    const float* tgt     = (const float*)d_in[3];
    const float* Wq      = (const float*)d_in[4];
    const float* bq      = (const float*)d_in[5];
    const float* Wk      = (const float*)d_in[6];
    const float* bk      = (const float*)d_in[7];
    float* out = (float*)d_out;

    const int corr_elems = BB * 3 * NN;
    const bool tuple_out = (out_size >= 2 * corr_elems);
    float* corr_out = tuple_out ? (out + corr_elems) : out;

    dim3 pg(NN / 64, EE / 128, BB);
    proj_kernel<<<pg, 256>>>(src_emb, Wq, bq, 0);
    proj_kernel<<<pg, 256>>>(tgt_emb, Wk, bk, 1);
    kk_kernel<<<BB * MM / 8, 256>>>();

    cudaFuncSetAttribute(attn_kernel, cudaFuncAttributeMaxDynamicSharedMemorySize,
                         SMEM_TOTAL);
    attn_kernel<<<128, 256, SMEM_TOTAL>>>(tgt);

    merge_kernel<<<(BB * NN + 255) / 256, 256>>>(corr_out);
    if (tuple_out)
        copy_src_kernel<<<(corr_elems + 255) / 256, 256>>>(src, out);
}